// round 10
// baseline (speedup 1.0000x reference)
#include <cuda_runtime.h>
#include <cuda_bf16.h>
#include <math.h>
#include <cstdint>

// ---------------- problem constants ----------------
#define BB 2
#define LL 2048
#define DIM 2048
#define HK 16
#define HV 32
#define DK 128
#define DV 128
#define KCONV 4
#define KEY_DIM (HK*DK)            // 2048
#define VAL_DIM (HV*DV)            // 4096
#define CONV_DIM (2*KEY_DIM+VAL_DIM) // 8192
#define MTOT (BB*LL)               // 4096

// ---------------- scratch ----------------
__device__ float g_qkv [ (size_t)BB*LL*CONV_DIM ];
__device__ float g_conv[ (size_t)BB*LL*CONV_DIM ];
__device__ float g_z   [ (size_t)BB*LL*VAL_DIM  ];
__device__ float g_eg  [ (size_t)BB*LL*HV ];
__device__ float g_beta[ (size_t)BB*LL*HV ];
__device__ float g_o   [ (size_t)BB*LL*VAL_DIM  ];
// int8 two-slice packed tensors: per (row, kt64) 128B =
// [s1 k0..31 | s2 k0..31 | s1 k32..63 | s2 k32..63]
__device__ uint8_t g_xq   [ (size_t)MTOT*DIM*2 ];
__device__ uint8_t g_wqkvq[ (size_t)CONV_DIM*DIM*2 ];
__device__ uint8_t g_wzq  [ (size_t)VAL_DIM*DIM*2 ];
__device__ uint8_t g_woutq[ (size_t)DIM*VAL_DIM*2 ];
__device__ uint8_t g_oq   [ (size_t)MTOT*VAL_DIM*2 ];
// per-row scales
__device__ float g_xs   [ MTOT ];
__device__ float g_wqkvs[ CONV_DIM ];
__device__ float g_wzs  [ VAL_DIM ];
__device__ float g_wouts[ DIM ];
__device__ float g_os   [ MTOT ];

#define SLICE_SCALE 254.0f
#define INV_SLICE   (1.0f/254.0f)

// ================= helpers ==================================================
__device__ __forceinline__ uint32_t smem_u32(const void* p) {
    uint32_t a;
    asm("{ .reg .u64 t; cvta.to.shared.u64 t, %1; cvt.u32.u64 %0, t; }"
        : "=r"(a) : "l"(p));
    return a;
}
#define SWZ128(off) ((off) ^ (((off) >> 3) & 0x70))

#define LDMX4(r0, r1, r2, r3, addr) \
    asm volatile("ldmatrix.sync.aligned.m8n8.x4.shared.b16 {%0,%1,%2,%3}, [%4];" \
        : "=r"(r0), "=r"(r1), "=r"(r2), "=r"(r3) : "r"(addr))

#define MMA_S8(d, a, b) \
    asm volatile("mma.sync.aligned.m16n8k32.row.col.s32.s8.s8.s32 " \
        "{%0,%1,%2,%3}, {%4,%5,%6,%7}, {%8,%9}, {%0,%1,%2,%3};" \
        : "+r"((d)[0]), "+r"((d)[1]), "+r"((d)[2]), "+r"((d)[3]) \
        : "r"((a)[0]), "r"((a)[1]), "r"((a)[2]), "r"((a)[3]), \
          "r"((b)[0]), "r"((b)[1]))

#define CP_ASYNC16(smem, gmem) \
    asm volatile("cp.async.cg.shared.global [%0], [%1], 16;" \
                 :: "r"(smem), "l"(gmem) : "memory")
#define CP_COMMIT() asm volatile("cp.async.commit_group;" ::: "memory")
#define CP_WAIT(n)  asm volatile("cp.async.wait_group %0;" :: "n"(n) : "memory")

// quantize 4 consecutive floats into two packed s8 words (slice1, slice2)
__device__ __forceinline__ void quant4(const float* v, float inv, uint32_t& u1, uint32_t& u2)
{
    u1 = 0; u2 = 0;
#pragma unroll
    for (int i = 0; i < 4; ++i) {
        float q  = v[i] * inv;                // in [-127, 127]
        float x1 = rintf(q);
        int  i1  = (int)x1;
        int  i2  = (int)rintf((q - x1) * SLICE_SCALE);
        u1 |= ((uint32_t)(i1 & 0xff)) << (8*i);
        u2 |= ((uint32_t)(i2 & 0xff)) << (8*i);
    }
}

// ------------- row quantization: one CTA per row -----------------------------
__global__ void __launch_bounds__(256) rowquant_kernel(const float* __restrict__ X,
                                                       uint8_t* __restrict__ Xq,
                                                       float* __restrict__ S,
                                                       int K)
{
    __shared__ float red[8];
    __shared__ float s_scale;
    const int row = blockIdx.x;
    const int t   = threadIdx.x;
    const int G   = K >> 8;                // floats per thread (8 or 16)
    const float* xp = X + (size_t)row * K + t * G;

    float v[16];
#pragma unroll 4
    for (int i = 0; i < G; i += 4)
        *(float4*)&v[i] = *(const float4*)&xp[i];

    float m = 0.f;
#pragma unroll
    for (int i = 0; i < G; ++i) m = fmaxf(m, fabsf(v[i]));
#pragma unroll
    for (int o = 16; o; o >>= 1) m = fmaxf(m, __shfl_xor_sync(0xffffffffu, m, o));
    if ((t & 31) == 0) red[t >> 5] = m;
    __syncthreads();
    if (t == 0) {
        float mm = red[0];
#pragma unroll
        for (int i = 1; i < 8; ++i) mm = fmaxf(mm, red[i]);
        float sc = (mm > 0.f) ? (mm / 127.f) : 1.f;
        s_scale = sc;
        S[row] = sc;
    }
    __syncthreads();
    const float inv = 1.f / s_scale;

    uint8_t* rowp = Xq + (size_t)row * (2 * K);
#pragma unroll
    for (int j = 0; j < G; j += 4) {
        int k0 = t * G + j;
        int kt = k0 >> 6, sub = (k0 >> 5) & 1, off = k0 & 31;
        uint32_t u1, u2;
        quant4(&v[j], inv, u1, u2);
        *(uint32_t*)(rowp + kt*128 + sub*64 + off)      = u1;
        *(uint32_t*)(rowp + kt*128 + sub*64 + 32 + off) = u2;
    }
}

// ================= int8x2 GEMM, CTA 128x128, 512 thr, 3x64k stages ==========
// C[M,N] = s_a[m] s_b[n] (A1B1 + (A1B2+A2B1)/254)
#define STG_A 16384
#define STG_B 16384
#define STG_BYTES (STG_A + STG_B)          // 32768
#define GEMM_SMEM (3*STG_BYTES + 128)
#define GTHREADS 512

__device__ __forceinline__ void gemm_s8(const uint8_t* __restrict__ Aq,
                                        const float* __restrict__ Sa,
                                        const uint8_t* __restrict__ Bq,
                                        const float* __restrict__ Sb,
                                        float* __restrict__ C,
                                        int N, int K, int bm, int bn, char* sm)
{
    const int tid  = threadIdx.x;          // 0..511
    const int lane = tid & 31;
    const int wid  = tid >> 5;             // 0..15
    const int wm = wid & 3;                // 4 m groups of 32 rows
    const int wn = wid >> 2;               // 4 n groups of 32 cols
    const uint32_t smb = (smem_u32(sm) + 127u) & ~127u;
    const int KTB = K >> 6;                // 64-k tiles (= 128B per row)

    // cp.async: thread t loads row t>>2, 16B chunks (t&3) and (t&3)+4
    const int rr = tid >> 2;
    const int c0 = (tid & 3) * 16;
    const uint32_t sA0 = SWZ128((uint32_t)(rr*128 + c0));
    const uint32_t sA1 = SWZ128((uint32_t)(rr*128 + c0 + 64));
    const uint8_t* Apb = Aq + ((size_t)bm * 128 + rr) * (size_t)KTB * 128 + c0;
    const uint8_t* Bpb = Bq + ((size_t)bn * 128 + rr) * (size_t)KTB * 128 + c0;

    const int lrow  = ((lane >> 3) & 1) * 8 + (lane & 7);
    const int lkofB = (lane >> 4) * 16;    // bytes

    int acc1[2][4][4], acc2[2][4][4];
#pragma unroll
    for (int i = 0; i < 2; ++i)
#pragma unroll
        for (int j = 0; j < 4; ++j)
#pragma unroll
            for (int r = 0; r < 4; ++r) { acc1[i][j][r] = 0; acc2[i][j][r] = 0; }

    auto issue_stage = [&](int kt64, uint32_t sbase) {
        CP_ASYNC16(sbase + sA0,         Apb + (size_t)kt64*128);
        CP_ASYNC16(sbase + sA1,         Apb + (size_t)kt64*128 + 64);
        CP_ASYNC16(sbase + STG_A + sA0, Bpb + (size_t)kt64*128);
        CP_ASYNC16(sbase + STG_A + sA1, Bpb + (size_t)kt64*128 + 64);
    };

    issue_stage(0, smb);
    CP_COMMIT();
    issue_stage(1, smb + STG_BYTES);
    CP_COMMIT();

    for (int kt = 0; kt < KTB; ++kt) {
        CP_WAIT(1);
        __syncthreads();

        if (kt + 2 < KTB) issue_stage(kt + 2, smb + ((kt + 2) % 3) * STG_BYTES);
        CP_COMMIT();

        const uint32_t sa = smb + (kt % 3) * STG_BYTES;
        const uint32_t sb = sa + STG_A;
#pragma unroll
        for (int sub = 0; sub < 2; ++sub) {
            const uint32_t kb = (uint32_t)(sub*64 + lkofB);
            // A fragments: 2 m-tiles x 2 slices
            uint32_t a1[2][4], a2[2][4];
#pragma unroll
            for (int mt = 0; mt < 2; ++mt) {
                uint32_t base = (uint32_t)((wm*32 + mt*16 + lrow)*128) + kb;
                LDMX4(a1[mt][0], a1[mt][1], a1[mt][2], a1[mt][3], sa + SWZ128(base));
                LDMX4(a2[mt][0], a2[mt][1], a2[mt][2], a2[mt][3], sa + SWZ128(base + 32));
            }
#pragma unroll
            for (int g = 0; g < 2; ++g) {
                uint32_t base = (uint32_t)((wn*32 + g*16 + lrow)*128) + kb;
                uint32_t b1a[2], b1b[2], b2a[2], b2b[2];
                {
                    uint32_t t0, t1, t2, t3;
                    LDMX4(t0, t1, t2, t3, sb + SWZ128(base));
                    b1a[0] = t0; b1a[1] = t2; b1b[0] = t1; b1b[1] = t3;
                    LDMX4(t0, t1, t2, t3, sb + SWZ128(base + 32));
                    b2a[0] = t0; b2a[1] = t2; b2b[0] = t1; b2b[1] = t3;
                }
                const int n0 = 2*g, n1 = 2*g + 1;
                // term-major: long dependency distance per accumulator
                MMA_S8(acc1[0][n0], a1[0], b1a);
                MMA_S8(acc1[1][n0], a1[1], b1a);
                MMA_S8(acc1[0][n1], a1[0], b1b);
                MMA_S8(acc1[1][n1], a1[1], b1b);
                MMA_S8(acc2[0][n0], a1[0], b2a);
                MMA_S8(acc2[1][n0], a1[1], b2a);
                MMA_S8(acc2[0][n1], a1[0], b2b);
                MMA_S8(acc2[1][n1], a1[1], b2b);
                MMA_S8(acc2[0][n0], a2[0], b1a);
                MMA_S8(acc2[1][n0], a2[1], b1a);
                MMA_S8(acc2[0][n1], a2[0], b1b);
                MMA_S8(acc2[1][n1], a2[1], b1b);
            }
        }
    }

    // epilogue with scale rescaling
    const int m0 = bm*128 + wm*32 + (lane >> 2);
    const int n0 = bn*128 + wn*32 + 2*(lane & 3);
#pragma unroll
    for (int mt = 0; mt < 2; ++mt) {
        const float sa0 = Sa[m0 + mt*16];
        const float sa1 = Sa[m0 + mt*16 + 8];
#pragma unroll
        for (int nt = 0; nt < 4; ++nt) {
            const float sb0 = Sb[n0 + nt*8];
            const float sb1 = Sb[n0 + nt*8 + 1];
            float f0 = (float)acc1[mt][nt][0] + (float)acc2[mt][nt][0]*INV_SLICE;
            float f1 = (float)acc1[mt][nt][1] + (float)acc2[mt][nt][1]*INV_SLICE;
            float f2 = (float)acc1[mt][nt][2] + (float)acc2[mt][nt][2]*INV_SLICE;
            float f3 = (float)acc1[mt][nt][3] + (float)acc2[mt][nt][3]*INV_SLICE;
            float* c0p = C + (size_t)(m0 + mt*16) * N + n0 + nt*8;
            *(float2*)c0p = make_float2(sa0*sb0*f0, sa0*sb1*f1);
            float* c1p = c0p + (size_t)8 * N;
            *(float2*)c1p = make_float2(sa1*sb0*f2, sa1*sb1*f3);
        }
    }
}

// merged qkv+z projection: bn 0..63 -> qkv, 64..95 -> z
__global__ void __launch_bounds__(GTHREADS, 1) gemm_qkvz_k(const uint8_t* __restrict__ xq,
                                                           const uint8_t* __restrict__ wqkvq,
                                                           const uint8_t* __restrict__ wzq,
                                                           float* __restrict__ qkv,
                                                           float* __restrict__ z)
{
    extern __shared__ char sm[];
    const int bn = blockIdx.x;
    if (bn < CONV_DIM/128)
        gemm_s8(xq, g_xs, wqkvq, g_wqkvs, qkv, CONV_DIM, DIM, blockIdx.y, bn, sm);
    else
        gemm_s8(xq, g_xs, wzq, g_wzs, z, VAL_DIM, DIM, blockIdx.y, bn - CONV_DIM/128, sm);
}

__global__ void __launch_bounds__(GTHREADS, 1) gemm_out_k(const uint8_t* __restrict__ oq,
                                                          const uint8_t* __restrict__ woutq,
                                                          float* __restrict__ C)
{
    extern __shared__ char sm[];
    gemm_s8(oq, g_os, woutq, g_wouts, C, DIM, VAL_DIM, blockIdx.y, blockIdx.x, sm);
}

// ------------- small GEMM for a/b + fused g/beta epilogue -------------------
__global__ void __launch_bounds__(256) ab_gemm(const float* __restrict__ x,
                                               const float* __restrict__ Wa,
                                               const float* __restrict__ Wb,
                                               const float* __restrict__ A_log,
                                               const float* __restrict__ dt_bias,
                                               float* __restrict__ eg_out,
                                               float* __restrict__ beta_out)
{
    __shared__ float xs[16][65];
    __shared__ float ws[64][65];
    const int tid = threadIdx.x;
    const int m0  = blockIdx.x * 16;

    float acc[4] = {0.f, 0.f, 0.f, 0.f};
    const int r  = tid & 15;
    const int jg = tid >> 4;

    for (int k0 = 0; k0 < DIM; k0 += 64) {
        {
            int rr = tid >> 4;
            int cc = (tid & 15) * 4;
            float4 v = *(const float4*)&x[(size_t)(m0+rr)*DIM + k0 + cc];
            xs[rr][cc] = v.x; xs[rr][cc+1] = v.y; xs[rr][cc+2] = v.z; xs[rr][cc+3] = v.w;
        }
#pragma unroll
        for (int u = 0; u < 4; ++u) {
            int idx = tid + u*256;
            int j  = idx >> 4;
            int cc = (idx & 15) * 4;
            const float* W = (j < 32) ? &Wa[(size_t)j*DIM] : &Wb[(size_t)(j-32)*DIM];
            float4 v = *(const float4*)&W[k0 + cc];
            ws[j][cc] = v.x; ws[j][cc+1] = v.y; ws[j][cc+2] = v.z; ws[j][cc+3] = v.w;
        }
        __syncthreads();
#pragma unroll 8
        for (int k = 0; k < 64; ++k) {
            float xv = xs[r][k];
            acc[0] += xv * ws[jg*4+0][k];
            acc[1] += xv * ws[jg*4+1][k];
            acc[2] += xv * ws[jg*4+2][k];
            acc[3] += xv * ws[jg*4+3][k];
        }
        __syncthreads();
    }
    const int m = m0 + r;
#pragma unroll
    for (int u = 0; u < 4; ++u) {
        int j = jg*4 + u;
        float v = acc[u];
        if (j < 32) {
            float sp = v + dt_bias[j];
            sp = (sp > 20.f) ? sp : log1pf(expf(sp));
            eg_out[(size_t)m*HV + j] = expf(-expf(A_log[j]) * sp);
        } else {
            beta_out[(size_t)m*HV + (j-32)] = 1.f / (1.f + expf(-v));
        }
    }
}

// ------------- depthwise causal conv (K=4) + SiLU ---------------------------
__global__ void __launch_bounds__(256) conv_silu_kernel(const float* __restrict__ in,
                                                        float* __restrict__ out,
                                                        const float* __restrict__ w)
{
    const int c  = blockIdx.x * 256 + threadIdx.x;
    const int lc = blockIdx.y;
    const int b  = blockIdx.z;
    const float w0 = w[c*4+0], w1 = w[c*4+1], w2 = w[c*4+2], w3 = w[c*4+3];
    const float* ip = in  + (size_t)b*LL*CONV_DIM + c;
    float*       op = out + (size_t)b*LL*CONV_DIM + c;
    const int l0 = lc * 128;
    float xm3, xm2, xm1;
    if (l0 == 0) { xm3 = xm2 = xm1 = 0.f; }
    else {
        xm3 = ip[(size_t)(l0-3)*CONV_DIM];
        xm2 = ip[(size_t)(l0-2)*CONV_DIM];
        xm1 = ip[(size_t)(l0-1)*CONV_DIM];
    }
#pragma unroll 4
    for (int l = l0; l < l0 + 128; ++l) {
        float x0 = ip[(size_t)l*CONV_DIM];
        float h = xm3*w0 + xm2*w1 + xm1*w2 + x0*w3;
        h = h / (1.f + expf(-h));
        op[(size_t)l*CONV_DIM] = h;
        xm3 = xm2; xm2 = xm1; xm1 = x0;
    }
}

// ------------- l2norm of q and k heads (in place) ---------------------------
__global__ void __launch_bounds__(256) qknorm_kernel(float* __restrict__ d)
{
    const int wid  = (blockIdx.x * blockDim.x + threadIdx.x) >> 5;
    const int lane = threadIdx.x & 31;
    const int h2 = wid & 31;
    const int l  = (wid >> 5) & (LL-1);
    const int b  = wid >> 16;
    float* p = d + ((size_t)(b*LL + l))*CONV_DIM + h2*128 + lane*4;
    float4 v = *(float4*)p;
    float ss = v.x*v.x + v.y*v.y + v.z*v.z + v.w*v.w;
#pragma unroll
    for (int o = 16; o; o >>= 1) ss += __shfl_xor_sync(0xffffffffu, ss, o);
    float r = rsqrtf(ss + 1e-6f);
    if (h2 < 16) r *= 0.08838834764831845f;
    v.x *= r; v.y *= r; v.z *= r; v.w *= r;
    *(float4*)p = v;
}

// ------------- gated delta rule scan ----------------------------------------
__global__ void __launch_bounds__(256, 1) scan_kernel(const float* __restrict__ qkv,
                                                      const float* __restrict__ eg,
                                                      const float* __restrict__ beta,
                                                      float* __restrict__ o)
{
    const int bi = blockIdx.x;
    const int vh = bi & 1;
    const int h  = (bi >> 1) & 31;
    const int b  = bi >> 6;
    const int hk = h >> 1;
    const int t  = threadIdx.x;
    const int kq   = t & 3;
    const int vloc = t >> 2;
    const int vcol = vh*64 + vloc;

    __shared__ float kq_s[2][256];
    __shared__ float egs[LL];
    __shared__ float bets[LL];

    for (int i = t; i < LL; i += 256) {
        egs[i]  = eg  [(size_t)(b*LL + i)*HV + h];
        bets[i] = beta[(size_t)(b*LL + i)*HV + h];
    }

    float s[32];
#pragma unroll
    for (int i = 0; i < 32; ++i) s[i] = 0.f;

    const float* base = qkv + (size_t)b*LL*CONV_DIM;
    const int kqoff = (t < 128) ? (KEY_DIM + hk*128 + t)
                                : (hk*128 + (t-128));
    const int voff  = 2*KEY_DIM + h*128 + vcol;
    float* optr = o + (size_t)b*LL*VAL_DIM + h*128 + vcol;

    kq_s[0][t] = base[kqoff];
    float vcur = base[voff];
    __syncthreads();

    int p = 0;
    for (int l = 0; l < LL; ++l) {
        float kqn = 0.f, vn = 0.f;
        if (l + 1 < LL) {
            kqn = base[(size_t)(l+1)*CONV_DIM + kqoff];
            vn  = base[(size_t)(l+1)*CONV_DIM + voff];
        }
        const float egv = egs[l];
        const float bv  = bets[l];
        const float* ks = &kq_s[p][kq*32];
        const float* qs = &kq_s[p][128 + kq*32];

        float kv0 = 0.f, kv1 = 0.f, kv2 = 0.f, kv3 = 0.f;
#pragma unroll
        for (int i = 0; i < 8; ++i) {
            kv0 += ks[i]    * s[i];
            kv1 += ks[i+8]  * s[i+8];
            kv2 += ks[i+16] * s[i+16];
            kv3 += ks[i+24] * s[i+24];
        }
        float kv = (kv0 + kv1) + (kv2 + kv3);
        kv += __shfl_xor_sync(0xffffffffu, kv, 1);
        kv += __shfl_xor_sync(0xffffffffu, kv, 2);
        kv *= egv;
        const float delta = (vcur - kv) * bv;

        float o0 = 0.f, o1 = 0.f, o2 = 0.f, o3 = 0.f;
#pragma unroll
        for (int i = 0; i < 8; ++i) {
            s[i]    = egv*s[i]    + ks[i]*delta;    o0 += qs[i]*s[i];
            s[i+8]  = egv*s[i+8]  + ks[i+8]*delta;  o1 += qs[i+8]*s[i+8];
            s[i+16] = egv*s[i+16] + ks[i+16]*delta; o2 += qs[i+16]*s[i+16];
            s[i+24] = egv*s[i+24] + ks[i+24]*delta; o3 += qs[i+24]*s[i+24];
        }
        float outv = (o0 + o1) + (o2 + o3);
        outv += __shfl_xor_sync(0xffffffffu, outv, 1);
        outv += __shfl_xor_sync(0xffffffffu, outv, 2);
        if (kq == 0) optr[(size_t)l*VAL_DIM] = outv;

        kq_s[p^1][t] = kqn;
        vcur = vn;
        __syncthreads();
        p ^= 1;
    }
}

// ------------- gated RMSNorm + int8x2 quantize -------------------------------
// one CTA per token row m: 256 threads, 16 values each over VAL_DIM=4096
__global__ void __launch_bounds__(256) rmsgate_quant_kernel(const float* __restrict__ o,
                                                            const float* __restrict__ z,
                                                            const float* __restrict__ nw,
                                                            uint8_t* __restrict__ oq,
                                                            float* __restrict__ os)
{
    __shared__ float red[8];
    __shared__ float s_scale;
    const int m = blockIdx.x;
    const int t = threadIdx.x;
    const float* op = o + (size_t)m*VAL_DIM + t*16;
    const float* zp = z + (size_t)m*VAL_DIM + t*16;

    float ov[16], zv[16];
#pragma unroll
    for (int i = 0; i < 16; i += 4) {
        *(float4*)&ov[i] = *(const float4*)&op[i];
        *(float4*)&zv[i] = *(const float4*)&zp[i];
    }
    // per-head (128 vals = 8 threads) sum of squares
    float ss = 0.f;
#pragma unroll
    for (int i = 0; i < 16; ++i) ss += ov[i]*ov[i];
    ss += __shfl_xor_sync(0xffffffffu, ss, 1);
    ss += __shfl_xor_sync(0xffffffffu, ss, 2);
    ss += __shfl_xor_sync(0xffffffffu, ss, 4);
    const float r = rsqrtf(ss * (1.f/128.f) + 1e-6f);

    float g[16];
    float mx = 0.f;
    const int cbase = (t*16) & 127;
#pragma unroll
    for (int i = 0; i < 16; ++i) {
        float zz = zv[i];
        g[i] = ov[i] * r * nw[cbase + i] * (zz / (1.f + expf(-zz)));
        mx = fmaxf(mx, fabsf(g[i]));
    }
#pragma unroll
    for (int off = 16; off; off >>= 1) mx = fmaxf(mx, __shfl_xor_sync(0xffffffffu, mx, off));
    if ((t & 31) == 0) red[t >> 5] = mx;
    __syncthreads();
    if (t == 0) {
        float mm = red[0];
#pragma unroll
        for (int i = 1; i < 8; ++i) mm = fmaxf(mm, red[i]);
        float sc = (mm > 0.f) ? (mm / 127.f) : 1.f;
        s_scale = sc;
        os[m] = sc;
    }
    __syncthreads();
    const float inv = 1.f / s_scale;

    uint8_t* rowp = oq + (size_t)m * (2 * VAL_DIM);
#pragma unroll
    for (int j = 0; j < 16; j += 4) {
        int k0 = t*16 + j;
        int kt = k0 >> 6, sub = (k0 >> 5) & 1, off = k0 & 31;
        uint32_t u1, u2;
        quant4(&g[j], inv, u1, u2);
        *(uint32_t*)(rowp + kt*128 + sub*64 + off)      = u1;
        *(uint32_t*)(rowp + kt*128 + sub*64 + 32 + off) = u2;
    }
}

// ---------------- launch ----------------------------------------------------
extern "C" void kernel_launch(void* const* d_in, const int* in_sizes, int n_in,
                              void* d_out, int out_size)
{
    const float* x       = (const float*)d_in[0];
    const float* W_qkv   = (const float*)d_in[1];
    const float* W_z     = (const float*)d_in[2];
    const float* W_a     = (const float*)d_in[3];
    const float* W_b     = (const float*)d_in[4];
    const float* conv_w  = (const float*)d_in[5];
    const float* A_log   = (const float*)d_in[6];
    const float* dt_bias = (const float*)d_in[7];
    const float* norm_w  = (const float*)d_in[8];
    const float* W_out   = (const float*)d_in[9];
    float* out = (float*)d_out;

    float *qkv, *cnv, *z, *eg, *bet, *o, *xs, *wqkvs, *wzs, *wouts, *os;
    uint8_t *xq, *wqkvq, *wzq, *woutq, *oq;
    cudaGetSymbolAddress((void**)&qkv, g_qkv);
    cudaGetSymbolAddress((void**)&cnv, g_conv);
    cudaGetSymbolAddress((void**)&z,   g_z);
    cudaGetSymbolAddress((void**)&eg,  g_eg);
    cudaGetSymbolAddress((void**)&bet, g_beta);
    cudaGetSymbolAddress((void**)&o,   g_o);
    cudaGetSymbolAddress((void**)&xq,    g_xq);
    cudaGetSymbolAddress((void**)&wqkvq, g_wqkvq);
    cudaGetSymbolAddress((void**)&wzq,   g_wzq);
    cudaGetSymbolAddress((void**)&woutq, g_woutq);
    cudaGetSymbolAddress((void**)&oq,    g_oq);
    cudaGetSymbolAddress((void**)&xs,    g_xs);
    cudaGetSymbolAddress((void**)&wqkvs, g_wqkvs);
    cudaGetSymbolAddress((void**)&wzs,   g_wzs);
    cudaGetSymbolAddress((void**)&wouts, g_wouts);
    cudaGetSymbolAddress((void**)&os,    g_os);

    cudaFuncSetAttribute(gemm_qkvz_k, cudaFuncAttributeMaxDynamicSharedMemorySize, GEMM_SMEM);
    cudaFuncSetAttribute(gemm_out_k,  cudaFuncAttributeMaxDynamicSharedMemorySize, GEMM_SMEM);

    // 0) row quantization — merged GEMM is the 4th launch (ncu capture)
    rowquant_kernel<<<MTOT, 256>>>(x, xq, xs, DIM);
    rowquant_kernel<<<CONV_DIM, 256>>>(W_qkv, wqkvq, wqkvs, DIM);
    rowquant_kernel<<<VAL_DIM, 256>>>(W_z, wzq, wzs, DIM);
    // 1) merged qkv + z projection (int8x2)
    gemm_qkvz_k<<<dim3(CONV_DIM/128 + VAL_DIM/128, MTOT/128), GTHREADS, GEMM_SMEM>>>(
        xq, wqkvq, wzq, qkv, z);
    // 2) remaining quant + a/b
    rowquant_kernel<<<DIM, 256>>>(W_out, woutq, wouts, VAL_DIM);
    ab_gemm<<<MTOT/16, 256>>>(x, W_a, W_b, A_log, dt_bias, eg, bet);
    // 3) conv + qknorm
    conv_silu_kernel<<<dim3(CONV_DIM/256, LL/128, BB), 256>>>(qkv, cnv, conv_w);
    qknorm_kernel<<<(BB*LL*32)/8, 256>>>(cnv);
    // 4) scan
    scan_kernel<<<BB*HV*2, 256>>>(cnv, eg, bet, o);
    // 5) gated RMSNorm + quantize
    rmsgate_quant_kernel<<<MTOT, 256>>>(o, z, norm_w, oq, os);
    // 6) output projection (int8x2)
    gemm_out_k<<<dim3(DIM/128, MTOT/128), GTHREADS, GEMM_SMEM>>>(oq, woutq, out);
}

// round 11
// speedup vs baseline: 1.7263x; 1.7263x over previous
#include <cuda_runtime.h>
#include <cuda_bf16.h>
#include <math.h>
#include <cstdint>

// ---------------- problem constants ----------------
#define BB 2
#define LL 2048
#define DIM 2048
#define HK 16
#define HV 32
#define DK 128
#define DV 128
#define KCONV 4
#define KEY_DIM (HK*DK)            // 2048
#define VAL_DIM (HV*DV)            // 4096
#define CONV_DIM (2*KEY_DIM+VAL_DIM) // 8192
#define MTOT (BB*LL)               // 4096

// ---------------- scratch ----------------
__device__ float g_qkv [ (size_t)BB*LL*CONV_DIM ];
__device__ float g_conv[ (size_t)BB*LL*CONV_DIM ];
__device__ float g_z   [ (size_t)BB*LL*VAL_DIM  ];
__device__ float g_eg  [ (size_t)BB*LL*HV ];
__device__ float g_beta[ (size_t)BB*LL*HV ];
__device__ float g_o   [ (size_t)BB*LL*VAL_DIM  ];
__device__ __nv_bfloat16 g_xp   [ (size_t)MTOT*DIM*2 ];
__device__ __nv_bfloat16 g_wqkvp[ (size_t)CONV_DIM*DIM*2 ];
__device__ __nv_bfloat16 g_wzp  [ (size_t)VAL_DIM*DIM*2 ];
__device__ __nv_bfloat16 g_woutp[ (size_t)DIM*VAL_DIM*2 ];
__device__ __nv_bfloat16 g_op   [ (size_t)MTOT*VAL_DIM*2 ];

// ================= helpers ==================================================
__device__ __forceinline__ uint32_t smem_u32(const void* p) {
    uint32_t a;
    asm("{ .reg .u64 t; cvta.to.shared.u64 t, %1; cvt.u32.u64 %0, t; }"
        : "=r"(a) : "l"(p));
    return a;
}
#define SWZ128(off) ((off) ^ (((off) >> 3) & 0x70))

#define LDMX4(r0, r1, r2, r3, addr) \
    asm volatile("ldmatrix.sync.aligned.m8n8.x4.shared.b16 {%0,%1,%2,%3}, [%4];" \
        : "=r"(r0), "=r"(r1), "=r"(r2), "=r"(r3) : "r"(addr))

#define MMA_BF16(d, a, b) \
    asm volatile("mma.sync.aligned.m16n8k16.row.col.f32.bf16.bf16.f32 " \
        "{%0,%1,%2,%3}, {%4,%5,%6,%7}, {%8,%9}, {%0,%1,%2,%3};" \
        : "+f"((d)[0]), "+f"((d)[1]), "+f"((d)[2]), "+f"((d)[3]) \
        : "r"((a)[0]), "r"((a)[1]), "r"((a)[2]), "r"((a)[3]), \
          "r"((b)[0]), "r"((b)[1]))

#define CP_ASYNC16(smem, gmem) \
    asm volatile("cp.async.cg.shared.global [%0], [%1], 16;" \
                 :: "r"(smem), "l"(gmem) : "memory")
#define CP_COMMIT() asm volatile("cp.async.commit_group;" ::: "memory")
#define CP_WAIT(n)  asm volatile("cp.async.wait_group %0;" :: "n"(n) : "memory")

__device__ __forceinline__ void split_pair(float x, float y,
                                           uint32_t& hi, uint32_t& lo) {
    __nv_bfloat16 hx = __float2bfloat16(x);
    __nv_bfloat16 hy = __float2bfloat16(y);
    __nv_bfloat162 h(hx, hy);
    hi = *reinterpret_cast<uint32_t*>(&h);
    __nv_bfloat162 l(__float2bfloat16(x - __bfloat162float(hx)),
                     __float2bfloat16(y - __bfloat162float(hy)));
    lo = *reinterpret_cast<uint32_t*>(&l);
}

// ------------- pack: fp32 [R][K] -> bf16 hi/lo rows of 128B ------------------
__global__ void __launch_bounds__(256) pack_kernel(const float* __restrict__ X,
                                                   __nv_bfloat16* __restrict__ Xp,
                                                   int K)
{
    const int idx = blockIdx.x * 256 + threadIdx.x;
    const int kq  = K >> 2;
    const int r   = idx / kq;
    const int k0  = (idx - r * kq) * 4;
    const int kt  = k0 >> 5;
    const int j   = k0 & 31;
    float4 v = *(const float4*)&X[(size_t)r * K + k0];
    uint32_t h0, l0, h1, l1;
    split_pair(v.x, v.y, h0, l0);
    split_pair(v.z, v.w, h1, l1);
    size_t base = ((size_t)r * (K >> 5) + kt) * 64 + j;
    *(uint2*)&Xp[base]      = make_uint2(h0, h1);
    *(uint2*)&Xp[base + 32] = make_uint2(l0, l1);
}

// ================= bf16x3 GEMM, CTA 128x256, 512 threads, 64-k stages =======
#define SUB_A 16384
#define SUB_B 32768
#define SUB_BYTES (SUB_A + SUB_B)        // 49152
#define STAGE_BYTES (2*SUB_BYTES)        // 98304
#define GEMM_SMEM (2*STAGE_BYTES + 256)  // NSTAGE=2
#define GTHREADS 512

template<int KC>
__device__ __forceinline__ void gemm_k64(const __nv_bfloat16* __restrict__ Ap,
                                         const __nv_bfloat16* __restrict__ Bp,
                                         float* __restrict__ C,
                                         int N, int bm, int bn, char* sm)
{
    const int tid  = threadIdx.x;          // 0..511
    const int lane = tid & 31;
    const int wid  = tid >> 5;             // 0..15
    const int wm = wid & 3;                // 4 m groups of 32 rows
    const int wn = wid >> 2;               // 4 n groups of 64 cols
    const uint32_t smb = (smem_u32(sm) + 127u) & ~127u;
    constexpr int KT  = KC >> 5;
    constexpr int KT2 = KC >> 6;

    const int r0  = tid >> 3;              // 0..63
    const int g16 = (tid & 7) * 16;
    uint32_t soffA[2], soffB[4];
#pragma unroll
    for (int q = 0; q < 2; ++q) soffA[q] = SWZ128((uint32_t)((r0 + q*64)*128 + g16));
#pragma unroll
    for (int q = 0; q < 4; ++q) soffB[q] = SWZ128((uint32_t)((r0 + q*64)*128 + g16));
    const char* Apb = (const char*)Ap + ((size_t)bm * 128) * (size_t)KT * 128;
    const char* Bpb = (const char*)Bp + ((size_t)bn * 256) * (size_t)KT * 128;

    const int lrow = ((lane >> 3) & 1) * 8 + (lane & 7);
    const int lkof = (lane >> 4) * 8;

    float acc[2][8][4];
#pragma unroll
    for (int i = 0; i < 2; ++i)
#pragma unroll
        for (int j = 0; j < 8; ++j)
#pragma unroll
            for (int r = 0; r < 4; ++r) acc[i][j][r] = 0.f;

    auto issue_stage = [&](int kt2, uint32_t sbase) {
#pragma unroll
        for (int sub = 0; sub < 2; ++sub) {
            const int kt = kt2*2 + sub;
            const uint32_t sa = sbase + sub * SUB_BYTES;
#pragma unroll
            for (int q = 0; q < 2; ++q)
                CP_ASYNC16(sa + soffA[q], Apb + ((size_t)(r0 + q*64) * KT + kt) * 128 + g16);
#pragma unroll
            for (int q = 0; q < 4; ++q)
                CP_ASYNC16(sa + SUB_A + soffB[q], Bpb + ((size_t)(r0 + q*64) * KT + kt) * 128 + g16);
        }
    };

    issue_stage(0, smb);
    CP_COMMIT();

    for (int kt2 = 0; kt2 < KT2; ++kt2) {
        CP_WAIT(0);
        __syncthreads();

        if (kt2 + 1 < KT2) issue_stage(kt2 + 1, smb + ((kt2 + 1) & 1) * STAGE_BYTES);
        CP_COMMIT();

        const uint32_t stg = smb + (kt2 & 1) * STAGE_BYTES;
#pragma unroll
        for (int sub = 0; sub < 2; ++sub) {
            const uint32_t sa = stg + sub * SUB_BYTES;
            const uint32_t sb = sa + SUB_A;
#pragma unroll
            for (int ks = 0; ks < 32; ks += 16) {
                uint32_t ah[2][4], al[2][4];
#pragma unroll
                for (int mt = 0; mt < 2; ++mt) {
                    uint32_t pre = (uint32_t)((wm*32 + mt*16 + lrow)*128 + (ks + lkof)*2);
                    uint32_t swz = SWZ128(pre);
                    LDMX4(ah[mt][0], ah[mt][1], ah[mt][2], ah[mt][3], sa + swz);
                    LDMX4(al[mt][0], al[mt][1], al[mt][2], al[mt][3], sa + (swz^64));
                }
                uint32_t bh[8][2], bl[8][2];
#pragma unroll
                for (int g = 0; g < 4; ++g) {
                    uint32_t pre = (uint32_t)((wn*64 + g*16 + lrow)*128 + (ks + lkof)*2);
                    uint32_t swz = SWZ128(pre);
                    uint32_t t0, t1, t2, t3;
                    LDMX4(t0, t1, t2, t3, sb + swz);
                    bh[2*g][0] = t0; bh[2*g][1] = t2;
                    bh[2*g+1][0] = t1; bh[2*g+1][1] = t3;
                    LDMX4(t0, t1, t2, t3, sb + (swz^64));
                    bl[2*g][0] = t0; bl[2*g][1] = t2;
                    bl[2*g+1][0] = t1; bl[2*g+1][1] = t3;
                }
                // term-major ordering: accumulator reuse separated by 15 MMAs
#pragma unroll
                for (int nt = 0; nt < 8; ++nt) {
                    MMA_BF16(acc[0][nt], ah[0], bh[nt]);
                    MMA_BF16(acc[1][nt], ah[1], bh[nt]);
                }
#pragma unroll
                for (int nt = 0; nt < 8; ++nt) {
                    MMA_BF16(acc[0][nt], ah[0], bl[nt]);
                    MMA_BF16(acc[1][nt], ah[1], bl[nt]);
                }
#pragma unroll
                for (int nt = 0; nt < 8; ++nt) {
                    MMA_BF16(acc[0][nt], al[0], bh[nt]);
                    MMA_BF16(acc[1][nt], al[1], bh[nt]);
                }
            }
        }
    }

    const int m0 = bm*128 + wm*32 + (lane >> 2);
    const int n0 = bn*256 + wn*64 + 2*(lane & 3);
#pragma unroll
    for (int mt = 0; mt < 2; ++mt)
#pragma unroll
        for (int nt = 0; nt < 8; ++nt) {
            float* c0 = C + (size_t)(m0 + mt*16) * N + n0 + nt*8;
            *(float2*)c0 = make_float2(acc[mt][nt][0], acc[mt][nt][1]);
            float* c1 = c0 + (size_t)8 * N;
            *(float2*)c1 = make_float2(acc[mt][nt][2], acc[mt][nt][3]);
        }
}

// merged qkv+z projection: bn 0..31 -> qkv, 32..47 -> z
__global__ void __launch_bounds__(GTHREADS, 1) gemm_qkvz(const __nv_bfloat16* __restrict__ xp,
                                                         const __nv_bfloat16* __restrict__ wqkvp,
                                                         const __nv_bfloat16* __restrict__ wzp,
                                                         float* __restrict__ qkv,
                                                         float* __restrict__ z)
{
    extern __shared__ char sm[];
    const int bn = blockIdx.x;
    if (bn < CONV_DIM/256)
        gemm_k64<DIM>(xp, wqkvp, qkv, CONV_DIM, blockIdx.y, bn, sm);
    else
        gemm_k64<DIM>(xp, wzp, z, VAL_DIM, blockIdx.y, bn - CONV_DIM/256, sm);
}

__global__ void __launch_bounds__(GTHREADS, 1) gemm_out(const __nv_bfloat16* __restrict__ Ap,
                                                        const __nv_bfloat16* __restrict__ Bp,
                                                        float* __restrict__ C)
{
    extern __shared__ char sm[];
    gemm_k64<VAL_DIM>(Ap, Bp, C, DIM, blockIdx.y, blockIdx.x, sm);
}

// ------------- small GEMM for a/b + fused g/beta epilogue -------------------
__global__ void __launch_bounds__(256) ab_gemm(const float* __restrict__ x,
                                               const float* __restrict__ Wa,
                                               const float* __restrict__ Wb,
                                               const float* __restrict__ A_log,
                                               const float* __restrict__ dt_bias,
                                               float* __restrict__ eg_out,
                                               float* __restrict__ beta_out)
{
    __shared__ float xs[16][65];
    __shared__ float ws[64][65];
    const int tid = threadIdx.x;
    const int m0  = blockIdx.x * 16;

    float acc[4] = {0.f, 0.f, 0.f, 0.f};
    const int r  = tid & 15;
    const int jg = tid >> 4;

    for (int k0 = 0; k0 < DIM; k0 += 64) {
        {
            int rr = tid >> 4;
            int cc = (tid & 15) * 4;
            float4 v = *(const float4*)&x[(size_t)(m0+rr)*DIM + k0 + cc];
            xs[rr][cc] = v.x; xs[rr][cc+1] = v.y; xs[rr][cc+2] = v.z; xs[rr][cc+3] = v.w;
        }
#pragma unroll
        for (int u = 0; u < 4; ++u) {
            int idx = tid + u*256;
            int j  = idx >> 4;
            int cc = (idx & 15) * 4;
            const float* W = (j < 32) ? &Wa[(size_t)j*DIM] : &Wb[(size_t)(j-32)*DIM];
            float4 v = *(const float4*)&W[k0 + cc];
            ws[j][cc] = v.x; ws[j][cc+1] = v.y; ws[j][cc+2] = v.z; ws[j][cc+3] = v.w;
        }
        __syncthreads();
#pragma unroll 8
        for (int k = 0; k < 64; ++k) {
            float xv = xs[r][k];
            acc[0] += xv * ws[jg*4+0][k];
            acc[1] += xv * ws[jg*4+1][k];
            acc[2] += xv * ws[jg*4+2][k];
            acc[3] += xv * ws[jg*4+3][k];
        }
        __syncthreads();
    }
    const int m = m0 + r;
#pragma unroll
    for (int u = 0; u < 4; ++u) {
        int j = jg*4 + u;
        float v = acc[u];
        if (j < 32) {
            float sp = v + dt_bias[j];
            sp = (sp > 20.f) ? sp : log1pf(expf(sp));
            eg_out[(size_t)m*HV + j] = expf(-expf(A_log[j]) * sp);
        } else {
            beta_out[(size_t)m*HV + (j-32)] = 1.f / (1.f + expf(-v));
        }
    }
}

// ------------- fused conv+SiLU+l2norm for q/k heads --------------------------
// warp = (b, head h2 in 0..31, L-chunk of 256). lanes: 4 channels each.
__global__ void __launch_bounds__(256) convnorm_qk_kernel(const float* __restrict__ in,
                                                          float* __restrict__ out,
                                                          const float* __restrict__ w)
{
    const int gw   = blockIdx.x * 8 + (threadIdx.x >> 5);   // 0..511
    const int lane = threadIdx.x & 31;
    const int chunk = gw & 7;
    const int h2    = (gw >> 3) & 31;
    const int b     = gw >> 8;
    const int c     = h2*128 + lane*4;     // q: h2<16 (c<2048); k: h2>=16

    // per-channel conv weights (4 channels x 4 taps)
    float4 wt[4];
#pragma unroll
    for (int i = 0; i < 4; ++i)
        wt[i] = *(const float4*)&w[(c + i)*4];

    const float* ip = in  + (size_t)b*LL*CONV_DIM + c;
    float*       op = out + (size_t)b*LL*CONV_DIM + c;
    const int l0 = chunk * 256;

    float4 xm3, xm2, xm1;
    if (l0 == 0) {
        xm3 = make_float4(0.f,0.f,0.f,0.f);
        xm2 = xm3; xm1 = xm3;
    } else {
        xm3 = *(const float4*)(ip + (size_t)(l0-3)*CONV_DIM);
        xm2 = *(const float4*)(ip + (size_t)(l0-2)*CONV_DIM);
        xm1 = *(const float4*)(ip + (size_t)(l0-1)*CONV_DIM);
    }
    const float qscale = (h2 < 16) ? 0.08838834764831845f : 1.f;

    for (int l = l0; l < l0 + 256; ++l) {
        float4 x0 = *(const float4*)(ip + (size_t)l*CONV_DIM);
        float h0 = xm3.x*wt[0].x + xm2.x*wt[0].y + xm1.x*wt[0].z + x0.x*wt[0].w;
        float h1 = xm3.y*wt[1].x + xm2.y*wt[1].y + xm1.y*wt[1].z + x0.y*wt[1].w;
        float h2v= xm3.z*wt[2].x + xm2.z*wt[2].y + xm1.z*wt[2].z + x0.z*wt[2].w;
        float h3 = xm3.w*wt[3].x + xm2.w*wt[3].y + xm1.w*wt[3].z + x0.w*wt[3].w;
        h0 = h0 / (1.f + expf(-h0));
        h1 = h1 / (1.f + expf(-h1));
        h2v= h2v/ (1.f + expf(-h2v));
        h3 = h3 / (1.f + expf(-h3));
        float ss = h0*h0 + h1*h1 + h2v*h2v + h3*h3;
#pragma unroll
        for (int o = 16; o; o >>= 1) ss += __shfl_xor_sync(0xffffffffu, ss, o);
        const float r = rsqrtf(ss + 1e-6f) * qscale;
        *(float4*)(op + (size_t)l*CONV_DIM) = make_float4(h0*r, h1*r, h2v*r, h3*r);
        xm3 = xm2; xm2 = xm1; xm1 = x0;
    }
}

// ------------- depthwise causal conv (K=4) + SiLU for v channels -------------
__global__ void __launch_bounds__(256) conv_v_kernel(const float* __restrict__ in,
                                                     float* __restrict__ out,
                                                     const float* __restrict__ w)
{
    const int c  = 2*KEY_DIM + blockIdx.x * 256 + threadIdx.x;
    const int lc = blockIdx.y;
    const int b  = blockIdx.z;
    const float w0 = w[c*4+0], w1 = w[c*4+1], w2 = w[c*4+2], w3 = w[c*4+3];
    const float* ip = in  + (size_t)b*LL*CONV_DIM + c;
    float*       op = out + (size_t)b*LL*CONV_DIM + c;
    const int l0 = lc * 128;
    float xm3, xm2, xm1;
    if (l0 == 0) { xm3 = xm2 = xm1 = 0.f; }
    else {
        xm3 = ip[(size_t)(l0-3)*CONV_DIM];
        xm2 = ip[(size_t)(l0-2)*CONV_DIM];
        xm1 = ip[(size_t)(l0-1)*CONV_DIM];
    }
#pragma unroll 4
    for (int l = l0; l < l0 + 128; ++l) {
        float x0 = ip[(size_t)l*CONV_DIM];
        float h = xm3*w0 + xm2*w1 + xm1*w2 + x0*w3;
        h = h / (1.f + expf(-h));
        op[(size_t)l*CONV_DIM] = h;
        xm3 = xm2; xm2 = xm1; xm1 = x0;
    }
}

// ------------- gated delta rule scan ----------------------------------------
__global__ void __launch_bounds__(256, 1) scan_kernel(const float* __restrict__ qkv,
                                                      const float* __restrict__ eg,
                                                      const float* __restrict__ beta,
                                                      float* __restrict__ o)
{
    const int bi = blockIdx.x;
    const int vh = bi & 1;
    const int h  = (bi >> 1) & 31;
    const int b  = bi >> 6;
    const int hk = h >> 1;
    const int t  = threadIdx.x;
    const int kq   = t & 3;
    const int vloc = t >> 2;
    const int vcol = vh*64 + vloc;

    __shared__ float kq_s[2][256];
    __shared__ float egs[LL];
    __shared__ float bets[LL];

    for (int i = t; i < LL; i += 256) {
        egs[i]  = eg  [(size_t)(b*LL + i)*HV + h];
        bets[i] = beta[(size_t)(b*LL + i)*HV + h];
    }

    float s[32];
#pragma unroll
    for (int i = 0; i < 32; ++i) s[i] = 0.f;

    const float* base = qkv + (size_t)b*LL*CONV_DIM;
    const int kqoff = (t < 128) ? (KEY_DIM + hk*128 + t)
                                : (hk*128 + (t-128));
    const int voff  = 2*KEY_DIM + h*128 + vcol;
    float* optr = o + (size_t)b*LL*VAL_DIM + h*128 + vcol;

    kq_s[0][t] = base[kqoff];
    float vcur = base[voff];
    __syncthreads();

    int p = 0;
    for (int l = 0; l < LL; ++l) {
        float kqn = 0.f, vn = 0.f;
        if (l + 1 < LL) {
            kqn = base[(size_t)(l+1)*CONV_DIM + kqoff];
            vn  = base[(size_t)(l+1)*CONV_DIM + voff];
        }
        const float egv = egs[l];
        const float bv  = bets[l];
        const float* ks = &kq_s[p][kq*32];
        const float* qs = &kq_s[p][128 + kq*32];

        float kv0 = 0.f, kv1 = 0.f, kv2 = 0.f, kv3 = 0.f;
#pragma unroll
        for (int i = 0; i < 8; ++i) {
            kv0 += ks[i]    * s[i];
            kv1 += ks[i+8]  * s[i+8];
            kv2 += ks[i+16] * s[i+16];
            kv3 += ks[i+24] * s[i+24];
        }
        float kv = (kv0 + kv1) + (kv2 + kv3);
        kv += __shfl_xor_sync(0xffffffffu, kv, 1);
        kv += __shfl_xor_sync(0xffffffffu, kv, 2);
        kv *= egv;
        const float delta = (vcur - kv) * bv;

        float o0 = 0.f, o1 = 0.f, o2 = 0.f, o3 = 0.f;
#pragma unroll
        for (int i = 0; i < 8; ++i) {
            s[i]    = egv*s[i]    + ks[i]*delta;    o0 += qs[i]*s[i];
            s[i+8]  = egv*s[i+8]  + ks[i+8]*delta;  o1 += qs[i+8]*s[i+8];
            s[i+16] = egv*s[i+16] + ks[i+16]*delta; o2 += qs[i+16]*s[i+16];
            s[i+24] = egv*s[i+24] + ks[i+24]*delta; o3 += qs[i+24]*s[i+24];
        }
        float outv = (o0 + o1) + (o2 + o3);
        outv += __shfl_xor_sync(0xffffffffu, outv, 1);
        outv += __shfl_xor_sync(0xffffffffu, outv, 2);
        if (kq == 0) optr[(size_t)l*VAL_DIM] = outv;

        kq_s[p^1][t] = kqn;
        vcur = vn;
        __syncthreads();
        p ^= 1;
    }
}

// ------------- gated RMSNorm + pack to bf16 hi/lo ---------------------------
__global__ void __launch_bounds__(256) rmsgate_pack_kernel(const float* __restrict__ o,
                                                           const float* __restrict__ z,
                                                           const float* __restrict__ nw,
                                                           __nv_bfloat16* __restrict__ op)
{
    const int wid  = (blockIdx.x * blockDim.x + threadIdx.x) >> 5;
    const int lane = threadIdx.x & 31;
    const float* p  = o + (size_t)wid*128 + lane*4;
    const float* zp = z + (size_t)wid*128 + lane*4;
    float4 v = *(const float4*)p;
    float ss = v.x*v.x + v.y*v.y + v.z*v.z + v.w*v.w;
#pragma unroll
    for (int off = 16; off; off >>= 1) ss += __shfl_xor_sync(0xffffffffu, ss, off);
    const float r = rsqrtf(ss * (1.f/128.f) + 1e-6f);
    float4 zv = *(const float4*)zp;
    float4 w4 = *(const float4*)&nw[lane*4];
    float4 out;
    out.x = v.x * r * w4.x * (zv.x / (1.f + expf(-zv.x)));
    out.y = v.y * r * w4.y * (zv.y / (1.f + expf(-zv.y)));
    out.z = v.z * r * w4.z * (zv.z / (1.f + expf(-zv.z)));
    out.w = v.w * r * w4.w * (zv.w / (1.f + expf(-zv.w)));
    const int m = wid >> 5;
    const int h = wid & 31;
    const int c = h*128 + lane*4;
    const int kt = c >> 5, j = c & 31;
    uint32_t h0, l0, h1, l1;
    split_pair(out.x, out.y, h0, l0);
    split_pair(out.z, out.w, h1, l1);
    size_t base = ((size_t)m * (VAL_DIM >> 5) + kt) * 64 + j;
    *(uint2*)&op[base]      = make_uint2(h0, h1);
    *(uint2*)&op[base + 32] = make_uint2(l0, l1);
}

// ---------------- launch ----------------------------------------------------
extern "C" void kernel_launch(void* const* d_in, const int* in_sizes, int n_in,
                              void* d_out, int out_size)
{
    const float* x       = (const float*)d_in[0];
    const float* W_qkv   = (const float*)d_in[1];
    const float* W_z     = (const float*)d_in[2];
    const float* W_a     = (const float*)d_in[3];
    const float* W_b     = (const float*)d_in[4];
    const float* conv_w  = (const float*)d_in[5];
    const float* A_log   = (const float*)d_in[6];
    const float* dt_bias = (const float*)d_in[7];
    const float* norm_w  = (const float*)d_in[8];
    const float* W_out   = (const float*)d_in[9];
    float* out = (float*)d_out;

    float *qkv, *cnv, *z, *eg, *bet, *o;
    __nv_bfloat16 *xp, *wqkvp, *wzp, *woutp, *op;
    cudaGetSymbolAddress((void**)&qkv, g_qkv);
    cudaGetSymbolAddress((void**)&cnv, g_conv);
    cudaGetSymbolAddress((void**)&z,   g_z);
    cudaGetSymbolAddress((void**)&eg,  g_eg);
    cudaGetSymbolAddress((void**)&bet, g_beta);
    cudaGetSymbolAddress((void**)&o,   g_o);
    cudaGetSymbolAddress((void**)&xp,    g_xp);
    cudaGetSymbolAddress((void**)&wqkvp, g_wqkvp);
    cudaGetSymbolAddress((void**)&wzp,   g_wzp);
    cudaGetSymbolAddress((void**)&woutp, g_woutp);
    cudaGetSymbolAddress((void**)&op,    g_op);

    cudaFuncSetAttribute(gemm_qkvz, cudaFuncAttributeMaxDynamicSharedMemorySize, GEMM_SMEM);
    cudaFuncSetAttribute(gemm_out,  cudaFuncAttributeMaxDynamicSharedMemorySize, GEMM_SMEM);

    // 0) packs — merged GEMM is the 4th launch (ncu capture)
    pack_kernel<<<(MTOT*DIM/4)/256, 256>>>(x, xp, DIM);
    pack_kernel<<<((size_t)CONV_DIM*DIM/4)/256, 256>>>(W_qkv, wqkvp, DIM);
    pack_kernel<<<((size_t)VAL_DIM*DIM/4)/256, 256>>>(W_z, wzp, DIM);
    // 1) merged qkv + z projection
    gemm_qkvz<<<dim3(CONV_DIM/256 + VAL_DIM/256, MTOT/128), GTHREADS, GEMM_SMEM>>>(
        xp, wqkvp, wzp, qkv, z);
    // 2) remaining pack + a/b
    pack_kernel<<<((size_t)DIM*VAL_DIM/4)/256, 256>>>(W_out, woutp, VAL_DIM);
    ab_gemm<<<MTOT/16, 256>>>(x, W_a, W_b, A_log, dt_bias, eg, bet);
    // 3) fused conv+silu+l2norm (q/k) and conv+silu (v)
    convnorm_qk_kernel<<<64, 256>>>(qkv, cnv, conv_w);
    conv_v_kernel<<<dim3(VAL_DIM/256, LL/128, BB), 256>>>(qkv, cnv, conv_w);
    // 4) scan
    scan_kernel<<<BB*HV*2, 256>>>(cnv, eg, bet, o);
    // 5) gated RMSNorm + pack
    rmsgate_pack_kernel<<<(BB*LL*HV)/8, 256>>>(o, z, norm_w, op);
    // 6) output projection
    gemm_out<<<dim3(DIM/256, MTOT/128), GTHREADS, GEMM_SMEM>>>(op, woutp, out);
}